// round 4
// baseline (speedup 1.0000x reference)
#include <cuda_runtime.h>
#include <cuda_fp16.h>
#include <cstdint>

#define DI __device__ __forceinline__

// ---------------- problem dims ----------------
constexpr int Mdim = 16384;   // B*S
constexpr int Kdim = 2048;    // IN
constexpr int Ndim = 2048;    // OUT
constexpr int LR   = 128;     // L*R
constexpr int Rr   = 32;

// ---------------- scratch ----------------
__device__ uint4 g_xh_raw[(size_t)Mdim * Kdim * 2 / 16];   // fp16 x      (64 MB)
__device__ uint4 g_wh_raw[(size_t)Ndim * Kdim * 2 / 16];   // fp16 W_eff  (8 MB)

// ---------------- PTX helpers (family-portable only) ----------------
DI uint32_t smem_u32(const void* p) {
    uint32_t a;
    asm("{ .reg .u64 t; cvta.to.shared.u64 t, %1; cvt.u32.u64 %0, t; }" : "=r"(a) : "l"(p));
    return a;
}
DI void cp_async16(uint32_t dst, const void* src) {
    asm volatile("cp.async.cg.shared.global [%0], [%1], 16;" :: "r"(dst), "l"(src) : "memory");
}
DI void cp_commit() { asm volatile("cp.async.commit_group;" ::: "memory"); }
template <int Nn> DI void cp_wait() { asm volatile("cp.async.wait_group %0;" :: "n"(Nn) : "memory"); }

DI void ldmatrix_x4(uint32_t* r, uint32_t addr) {
    asm volatile("ldmatrix.sync.aligned.m8n8.x4.shared.b16 {%0,%1,%2,%3}, [%4];"
                 : "=r"(r[0]), "=r"(r[1]), "=r"(r[2]), "=r"(r[3]) : "r"(addr));
}
// f16-accumulate MMA: C/D are 2 b32 regs (4 halves)
DI void mma16816_h(uint32_t& c0, uint32_t& c1, const uint32_t* a, uint32_t b0, uint32_t b1) {
    asm volatile(
        "mma.sync.aligned.m16n8k16.row.col.f16.f16.f16.f16 "
        "{%0,%1}, {%2,%3,%4,%5}, {%6,%7}, {%0,%1};"
        : "+r"(c0), "+r"(c1)
        : "r"(a[0]), "r"(a[1]), "r"(a[2]), "r"(a[3]), "r"(b0), "r"(b1));
}
// swizzled byte offset within a [rows x 128B] tile
DI uint32_t tile_off(int row, int c) { return (uint32_t)(row * 128) + (uint32_t)(((c ^ (row & 7)) << 4)); }
DI uint32_t swz128(uint32_t b) { return b ^ ((b >> 3) & 0x70); }

// ============================================================
// Fused pre-pass kernel:
//   blocks [0, 1024):    W_eff = W + sum_l s_l * up_l @ down_l  -> fp16
//   blocks [1024, 5120): x fp32 -> fp16
// ============================================================
constexpr int WEFF_BLOCKS = (Ndim / 64) * (Kdim / 64);   // 1024
constexpr int CONV_BLOCKS = 4096;
constexpr int US_STRIDE = 68;
constexpr int PREP_SMEM = (LR * US_STRIDE + LR * 64) * 4;  // 67584 B

__global__ void __launch_bounds__(256) k_prep(const float* __restrict__ x,
                                              const float* __restrict__ weight,
                                              const float* __restrict__ downs,
                                              const float* __restrict__ ups,
                                              const float* __restrict__ scales) {
    const int tid = threadIdx.x;

    if (blockIdx.x >= WEFF_BLOCKS) {
        // ---- x conversion ----
        size_t i = (size_t)(blockIdx.x - WEFF_BLOCKS) * 256 + tid;
        const size_t stride = (size_t)CONV_BLOCKS * 256;
        const float4* x4 = (const float4*)x;
        uint2* o4 = (uint2*)g_xh_raw;
        const size_t n4 = (size_t)Mdim * Kdim / 4;
        for (; i < n4; i += stride) {
            float4 v = x4[i];
            __half2 a = __floats2half2_rn(v.x, v.y);
            __half2 b = __floats2half2_rn(v.z, v.w);
            uint2 u;
            u.x = *(uint32_t*)&a;
            u.y = *(uint32_t*)&b;
            o4[i] = u;
        }
        return;
    }

    // ---- W_eff tile: 64 (o) x 64 (i) ----
    extern __shared__ float wsm[];
    float* Us = wsm;                   // [128][US_STRIDE]
    float* Ds = wsm + LR * US_STRIDE;  // [128][64]
    const int I0 = (blockIdx.x & 31) * 64;
    const int O0 = (blockIdx.x >> 5) * 64;

    {
        const int r = tid & 31, ob = tid >> 5;
#pragma unroll
        for (int l = 0; l < 4; l++) {
            float s = scales[l];
            const float* up_l = ups + (size_t)l * Ndim * Rr;
#pragma unroll
            for (int it = 0; it < 8; it++) {
                int o = it * 8 + ob;
                Us[(l * 32 + r) * US_STRIDE + o] = s * up_l[(size_t)(O0 + o) * Rr + r];
            }
        }
    }
    for (int c = tid; c < LR * 16; c += 256) {
        int k = c >> 4, f = c & 15;
        *(float4*)&Ds[k * 64 + f * 4] = *(const float4*)&downs[(size_t)k * Kdim + I0 + f * 4];
    }
    __syncthreads();

    const int to = tid >> 4, ti = tid & 15;
    float acc[4][4];
#pragma unroll
    for (int a = 0; a < 4; a++)
#pragma unroll
        for (int b = 0; b < 4; b++) acc[a][b] = 0.f;

#pragma unroll 4
    for (int k = 0; k < LR; k++) {
        float4 u = *(const float4*)&Us[k * US_STRIDE + to * 4];
        float4 d = *(const float4*)&Ds[k * 64 + ti * 4];
        float uu[4] = {u.x, u.y, u.z, u.w};
        float dd[4] = {d.x, d.y, d.z, d.w};
#pragma unroll
        for (int a = 0; a < 4; a++)
#pragma unroll
            for (int b = 0; b < 4; b++) acc[a][b] += uu[a] * dd[b];
    }

    __half* gw = (__half*)g_wh_raw;
#pragma unroll
    for (int a = 0; a < 4; a++) {
        int o = O0 + to * 4 + a;
        float4 wv = *(const float4*)&weight[(size_t)o * Kdim + I0 + ti * 4];
        __half2 p0 = __floats2half2_rn(acc[a][0] + wv.x, acc[a][1] + wv.y);
        __half2 p1 = __floats2half2_rn(acc[a][2] + wv.z, acc[a][3] + wv.w);
        uint2 u;
        u.x = *(uint32_t*)&p0;
        u.y = *(uint32_t*)&p1;
        *(uint2*)&gw[(size_t)o * Kdim + I0 + ti * 4] = u;
    }
}

// ============================================================
// Main GEMM: y = xh @ Wh^T + bias
//   mma.sync.m16n8k16 with FP16 accumulation within each BK=64 chunk,
//   promoted to fp32 once per k-iter. BM=BN=128, BK=64, 3 stages,
//   8 warps (2x4), warp tile 64x32.
// ============================================================
constexpr int BK = 64;
constexpr int STAGES = 3;
constexpr int NK = Kdim / BK;                    // 32
constexpr int AB_BYTES = 128 * 128;              // 16 KB
constexpr int STG_BYTES = 2 * AB_BYTES;          // 32 KB
constexpr int GEMM_SMEM = STAGES * STG_BYTES;    // 96 KB

__global__ void __launch_bounds__(256, 2) k_gemm(const float* __restrict__ bias,
                                                 float* __restrict__ out) {
    extern __shared__ char smem[];
    const uint32_t sb = smem_u32(smem);
    const int tid = threadIdx.x;
    const int wid = tid >> 5, lane = tid & 31;
    const int M0 = blockIdx.y * 128, N0 = blockIdx.x * 128;

    const int warp_m = (wid & 1) * 64;
    const int warp_n = (wid >> 1) * 32;

    const __half* gA = (const __half*)g_xh_raw;
    const __half* gB = (const __half*)g_wh_raw;

    auto load_stage = [&](int s, int kk) {
        const uint32_t base = sb + s * STG_BYTES;
        const int k0 = kk * BK;
#pragma unroll
        for (int it = 0; it < 4; it++) {
            int c = tid + it * 256;
            int row = c >> 3, col = c & 7;
            cp_async16(base + swz128(row * 128 + col * 16),
                       gA + (size_t)(M0 + row) * Kdim + k0 + col * 8);
        }
#pragma unroll
        for (int it = 0; it < 4; it++) {
            int c = tid + it * 256;
            int row = c >> 3, col = c & 7;
            cp_async16(base + AB_BYTES + swz128(row * 128 + col * 16),
                       gB + (size_t)(N0 + row) * Kdim + k0 + col * 8);
        }
    };

    float acc[4][4][4];
#pragma unroll
    for (int mt = 0; mt < 4; mt++)
#pragma unroll
        for (int nt = 0; nt < 4; nt++)
#pragma unroll
            for (int c = 0; c < 4; c++) acc[mt][nt][c] = 0.f;

    load_stage(0, 0); cp_commit();
    load_stage(1, 1); cp_commit();

    const int lane15 = lane & 15;
    const int laneHi = lane >> 4;
    int rowA[4], rowB[2];
#pragma unroll
    for (int mt = 0; mt < 4; mt++) rowA[mt] = warp_m + mt * 16 + lane15;
#pragma unroll
    for (int np = 0; np < 2; np++) rowB[np] = warp_n + np * 16 + lane15;

    for (int k = 0; k < NK; k++) {
        cp_wait<STAGES - 2>();
        __syncthreads();

        const int kn = k + STAGES - 1;
        if (kn < NK) load_stage(kn % STAGES, kn);
        cp_commit();

        const int s = k % STAGES;
        const uint32_t Ab = sb + s * STG_BYTES;
        const uint32_t Bb = Ab + AB_BYTES;

        // fp16 accumulators for this BK=64 chunk
        uint32_t h0[4][4], h1[4][4];
#pragma unroll
        for (int mt = 0; mt < 4; mt++)
#pragma unroll
            for (int nt = 0; nt < 4; nt++) { h0[mt][nt] = 0u; h1[mt][nt] = 0u; }

#pragma unroll
        for (int ks = 0; ks < 4; ks++) {
            uint32_t a[4][4], b[2][4];
#pragma unroll
            for (int mt = 0; mt < 4; mt++)
                ldmatrix_x4(a[mt], Ab + tile_off(rowA[mt], ks * 2 + laneHi));
#pragma unroll
            for (int np = 0; np < 2; np++)
                ldmatrix_x4(b[np], Bb + tile_off(rowB[np], ks * 2 + laneHi));
#pragma unroll
            for (int mt = 0; mt < 4; mt++)
#pragma unroll
                for (int nt = 0; nt < 4; nt++) {
                    const int np = nt >> 1, half = nt & 1;
                    mma16816_h(h0[mt][nt], h1[mt][nt], a[mt], b[np][half], b[np][2 + half]);
                }
        }

        // promote chunk sums to fp32
#pragma unroll
        for (int mt = 0; mt < 4; mt++)
#pragma unroll
            for (int nt = 0; nt < 4; nt++) {
                float2 f0 = __half22float2(*(__half2*)&h0[mt][nt]);
                float2 f1 = __half22float2(*(__half2*)&h1[mt][nt]);
                acc[mt][nt][0] += f0.x;
                acc[mt][nt][1] += f0.y;
                acc[mt][nt][2] += f1.x;
                acc[mt][nt][3] += f1.y;
            }
    }

    // epilogue
    const int gq = lane >> 2, rq = lane & 3;
#pragma unroll
    for (int mt = 0; mt < 4; mt++) {
#pragma unroll
        for (int nt = 0; nt < 4; nt++) {
            int m = M0 + warp_m + mt * 16 + gq;
            int n = N0 + warp_n + nt * 8 + rq * 2;
            float2 bv = *(const float2*)&bias[n];
            float2 v0, v1;
            v0.x = acc[mt][nt][0] + bv.x;
            v0.y = acc[mt][nt][1] + bv.y;
            v1.x = acc[mt][nt][2] + bv.x;
            v1.y = acc[mt][nt][3] + bv.y;
            *(float2*)&out[(size_t)m * Ndim + n] = v0;
            *(float2*)&out[(size_t)(m + 8) * Ndim + n] = v1;
        }
    }
}

// ============================================================
// launch
// ============================================================
extern "C" void kernel_launch(void* const* d_in, const int* in_sizes, int n_in,
                              void* d_out, int out_size) {
    const float* x      = (const float*)d_in[0];
    const float* weight = (const float*)d_in[1];
    const float* bias   = (const float*)d_in[2];
    const float* downs  = (const float*)d_in[3];
    const float* ups    = (const float*)d_in[4];
    const float* scales = (const float*)d_in[5];
    float* out = (float*)d_out;

    cudaFuncSetAttribute(k_gemm, cudaFuncAttributeMaxDynamicSharedMemorySize, GEMM_SMEM);
    cudaFuncSetAttribute(k_prep, cudaFuncAttributeMaxDynamicSharedMemorySize, PREP_SMEM);

    k_prep<<<WEFF_BLOCKS + CONV_BLOCKS, 256, PREP_SMEM>>>(x, weight, downs, ups, scales);
    k_gemm<<<dim3(Ndim / 128, Mdim / 128), 256, GEMM_SMEM>>>(bias, out);
}

// round 6
// speedup vs baseline: 1.1656x; 1.1656x over previous
#include <cuda_runtime.h>
#include <cuda_fp16.h>
#include <cstdint>

#define DI __device__ __forceinline__

// ---------------- problem dims ----------------
constexpr int Mdim = 16384;   // B*S
constexpr int Kdim = 2048;    // IN
constexpr int Ndim = 2048;    // OUT
constexpr int LR   = 128;     // L*R
constexpr int Rr   = 32;

// ---------------- scratch ----------------
__device__ uint4 g_xh_raw[(size_t)Mdim * Kdim * 2 / 16];   // fp16 x      (64 MB)
__device__ uint4 g_wh_raw[(size_t)Ndim * Kdim * 2 / 16];   // fp16 W_eff  (8 MB)

// ---------------- PTX helpers (family-portable only) ----------------
DI uint32_t smem_u32(const void* p) {
    uint32_t a;
    asm("{ .reg .u64 t; cvta.to.shared.u64 t, %1; cvt.u32.u64 %0, t; }" : "=r"(a) : "l"(p));
    return a;
}
DI void cp_async16(uint32_t dst, const void* src) {
    asm volatile("cp.async.cg.shared.global [%0], [%1], 16;" :: "r"(dst), "l"(src) : "memory");
}
DI void cp_commit() { asm volatile("cp.async.commit_group;" ::: "memory"); }
template <int Nn> DI void cp_wait() { asm volatile("cp.async.wait_group %0;" :: "n"(Nn) : "memory"); }

DI void ldmatrix_x4(uint32_t* r, uint32_t addr) {
    asm volatile("ldmatrix.sync.aligned.m8n8.x4.shared.b16 {%0,%1,%2,%3}, [%4];"
                 : "=r"(r[0]), "=r"(r[1]), "=r"(r[2]), "=r"(r[3]) : "r"(addr));
}
DI void mma16816(float* c, const uint32_t* a, uint32_t b0, uint32_t b1) {
    asm volatile(
        "mma.sync.aligned.m16n8k16.row.col.f32.f16.f16.f32 "
        "{%0,%1,%2,%3}, {%4,%5,%6,%7}, {%8,%9}, {%0,%1,%2,%3};"
        : "+f"(c[0]), "+f"(c[1]), "+f"(c[2]), "+f"(c[3])
        : "r"(a[0]), "r"(a[1]), "r"(a[2]), "r"(a[3]), "r"(b0), "r"(b1));
}
// swizzled byte offset within a [rows x 128B] tile
DI uint32_t tile_off(int row, int c) { return (uint32_t)(row * 128) + (uint32_t)(((c ^ (row & 7)) << 4)); }
DI uint32_t swz128(uint32_t b) { return b ^ ((b >> 3) & 0x70); }

// ============================================================
// Fused pre-pass kernel:
//   blocks [0, 1024):    W_eff = W + sum_l s_l * up_l @ down_l  -> fp16
//   blocks [1024, 5120): x fp32 -> fp16
// ============================================================
constexpr int WEFF_BLOCKS = (Ndim / 64) * (Kdim / 64);   // 1024
constexpr int CONV_BLOCKS = 4096;
constexpr int US_STRIDE = 68;
constexpr int PREP_SMEM = (LR * US_STRIDE + LR * 64) * 4;  // 67584 B

__global__ void __launch_bounds__(256) k_prep(const float* __restrict__ x,
                                              const float* __restrict__ weight,
                                              const float* __restrict__ downs,
                                              const float* __restrict__ ups,
                                              const float* __restrict__ scales) {
    const int tid = threadIdx.x;

    if (blockIdx.x >= WEFF_BLOCKS) {
        size_t i = (size_t)(blockIdx.x - WEFF_BLOCKS) * 256 + tid;
        const size_t stride = (size_t)CONV_BLOCKS * 256;
        const float4* x4 = (const float4*)x;
        uint2* o4 = (uint2*)g_xh_raw;
        const size_t n4 = (size_t)Mdim * Kdim / 4;
        for (; i < n4; i += stride) {
            float4 v = x4[i];
            __half2 a = __floats2half2_rn(v.x, v.y);
            __half2 b = __floats2half2_rn(v.z, v.w);
            uint2 u;
            u.x = *(uint32_t*)&a;
            u.y = *(uint32_t*)&b;
            o4[i] = u;
        }
        return;
    }

    extern __shared__ float wsm[];
    float* Us = wsm;                   // [128][US_STRIDE]
    float* Ds = wsm + LR * US_STRIDE;  // [128][64]
    const int I0 = (blockIdx.x & 31) * 64;
    const int O0 = (blockIdx.x >> 5) * 64;

    {
        const int r = tid & 31, ob = tid >> 5;
#pragma unroll
        for (int l = 0; l < 4; l++) {
            float s = scales[l];
            const float* up_l = ups + (size_t)l * Ndim * Rr;
#pragma unroll
            for (int it = 0; it < 8; it++) {
                int o = it * 8 + ob;
                Us[(l * 32 + r) * US_STRIDE + o] = s * up_l[(size_t)(O0 + o) * Rr + r];
            }
        }
    }
    for (int c = tid; c < LR * 16; c += 256) {
        int k = c >> 4, f = c & 15;
        *(float4*)&Ds[k * 64 + f * 4] = *(const float4*)&downs[(size_t)k * Kdim + I0 + f * 4];
    }
    __syncthreads();

    const int to = tid >> 4, ti = tid & 15;
    float acc[4][4];
#pragma unroll
    for (int a = 0; a < 4; a++)
#pragma unroll
        for (int b = 0; b < 4; b++) acc[a][b] = 0.f;

#pragma unroll 4
    for (int k = 0; k < LR; k++) {
        float4 u = *(const float4*)&Us[k * US_STRIDE + to * 4];
        float4 d = *(const float4*)&Ds[k * 64 + ti * 4];
        float uu[4] = {u.x, u.y, u.z, u.w};
        float dd[4] = {d.x, d.y, d.z, d.w};
#pragma unroll
        for (int a = 0; a < 4; a++)
#pragma unroll
            for (int b = 0; b < 4; b++) acc[a][b] += uu[a] * dd[b];
    }

    __half* gw = (__half*)g_wh_raw;
#pragma unroll
    for (int a = 0; a < 4; a++) {
        int o = O0 + to * 4 + a;
        float4 wv = *(const float4*)&weight[(size_t)o * Kdim + I0 + ti * 4];
        __half2 p0 = __floats2half2_rn(acc[a][0] + wv.x, acc[a][1] + wv.y);
        __half2 p1 = __floats2half2_rn(acc[a][2] + wv.z, acc[a][3] + wv.w);
        uint2 u;
        u.x = *(uint32_t*)&p0;
        u.y = *(uint32_t*)&p1;
        *(uint2*)&gw[(size_t)o * Kdim + I0 + ti * 4] = u;
    }
}

// ============================================================
// Main GEMM: y = xh @ Wh^T + bias
//   mma.sync.m16n8k16 fp32 acc. BM=BN=128, BK=64, 3 stages.
//   128 threads = 4 warps (2x2), warp tile 64x64 -> 2x less LDSM dup.
// ============================================================
constexpr int BK = 64;
constexpr int STAGES = 3;
constexpr int NK = Kdim / BK;                    // 32
constexpr int AB_BYTES = 128 * 128;              // 16 KB
constexpr int STG_BYTES = 2 * AB_BYTES;          // 32 KB
constexpr int GEMM_SMEM = STAGES * STG_BYTES;    // 96 KB

__global__ void __launch_bounds__(128, 2) k_gemm(const float* __restrict__ bias,
                                                 float* __restrict__ out) {
    extern __shared__ char smem[];
    const uint32_t sb = smem_u32(smem);
    const int tid = threadIdx.x;
    const int wid = tid >> 5, lane = tid & 31;
    const int M0 = blockIdx.y * 128, N0 = blockIdx.x * 128;

    const int warp_m = (wid & 1) * 64;     // 2 warps along M
    const int warp_n = (wid >> 1) * 64;    // 2 warps along N

    const __half* gA = (const __half*)g_xh_raw;
    const __half* gB = (const __half*)g_wh_raw;

    auto load_stage = [&](int s, int kk) {
        const uint32_t base = sb + s * STG_BYTES;
        const int k0 = kk * BK;
#pragma unroll
        for (int it = 0; it < 8; it++) {
            int c = tid + it * 128;
            int row = c >> 3, col = c & 7;
            cp_async16(base + swz128(row * 128 + col * 16),
                       gA + (size_t)(M0 + row) * Kdim + k0 + col * 8);
        }
#pragma unroll
        for (int it = 0; it < 8; it++) {
            int c = tid + it * 128;
            int row = c >> 3, col = c & 7;
            cp_async16(base + AB_BYTES + swz128(row * 128 + col * 16),
                       gB + (size_t)(N0 + row) * Kdim + k0 + col * 8);
        }
    };

    float acc[4][8][4];
#pragma unroll
    for (int mt = 0; mt < 4; mt++)
#pragma unroll
        for (int nt = 0; nt < 8; nt++)
#pragma unroll
            for (int c = 0; c < 4; c++) acc[mt][nt][c] = 0.f;

    load_stage(0, 0); cp_commit();
    load_stage(1, 1); cp_commit();

    const int lane15 = lane & 15;
    const int laneHi = lane >> 4;
    int rowA[4], rowB[4];
#pragma unroll
    for (int mt = 0; mt < 4; mt++) rowA[mt] = warp_m + mt * 16 + lane15;
#pragma unroll
    for (int np = 0; np < 4; np++) rowB[np] = warp_n + np * 16 + lane15;

    for (int k = 0; k < NK; k++) {
        cp_wait<STAGES - 2>();
        __syncthreads();

        const int kn = k + STAGES - 1;
        if (kn < NK) load_stage(kn % STAGES, kn);
        cp_commit();

        const int s = k % STAGES;
        const uint32_t Ab = sb + s * STG_BYTES;
        const uint32_t Bb = Ab + AB_BYTES;

#pragma unroll
        for (int ks = 0; ks < 4; ks++) {
            uint32_t a[4][4], b[4][4];
#pragma unroll
            for (int mt = 0; mt < 4; mt++)
                ldmatrix_x4(a[mt], Ab + tile_off(rowA[mt], ks * 2 + laneHi));
#pragma unroll
            for (int np = 0; np < 4; np++)
                ldmatrix_x4(b[np], Bb + tile_off(rowB[np], ks * 2 + laneHi));
#pragma unroll
            for (int mt = 0; mt < 4; mt++)
#pragma unroll
                for (int nt = 0; nt < 8; nt++) {
                    const int np = nt >> 1, half = nt & 1;
                    mma16816(acc[mt][nt], a[mt], b[np][half], b[np][2 + half]);
                }
        }
    }

    // epilogue
    const int gq = lane >> 2, rq = lane & 3;
#pragma unroll
    for (int mt = 0; mt < 4; mt++) {
#pragma unroll
        for (int nt = 0; nt < 8; nt++) {
            int m = M0 + warp_m + mt * 16 + gq;
            int n = N0 + warp_n + nt * 8 + rq * 2;
            float2 bv = *(const float2*)&bias[n];
            float2 v0, v1;
            v0.x = acc[mt][nt][0] + bv.x;
            v0.y = acc[mt][nt][1] + bv.y;
            v1.x = acc[mt][nt][2] + bv.x;
            v1.y = acc[mt][nt][3] + bv.y;
            *(float2*)&out[(size_t)m * Ndim + n] = v0;
            *(float2*)&out[(size_t)(m + 8) * Ndim + n] = v1;
        }
    }
}

// ============================================================
// launch
// ============================================================
extern "C" void kernel_launch(void* const* d_in, const int* in_sizes, int n_in,
                              void* d_out, int out_size) {
    const float* x      = (const float*)d_in[0];
    const float* weight = (const float*)d_in[1];
    const float* bias   = (const float*)d_in[2];
    const float* downs  = (const float*)d_in[3];
    const float* ups    = (const float*)d_in[4];
    const float* scales = (const float*)d_in[5];
    float* out = (float*)d_out;

    cudaFuncSetAttribute(k_gemm, cudaFuncAttributeMaxDynamicSharedMemorySize, GEMM_SMEM);
    cudaFuncSetAttribute(k_prep, cudaFuncAttributeMaxDynamicSharedMemorySize, PREP_SMEM);

    k_prep<<<WEFF_BLOCKS + CONV_BLOCKS, 256, PREP_SMEM>>>(x, weight, downs, ups, scales);
    k_gemm<<<dim3(Ndim / 128, Mdim / 128), 128, GEMM_SMEM>>>(bias, out);
}

// round 7
// speedup vs baseline: 1.1729x; 1.0063x over previous
#include <cuda_runtime.h>
#include <cuda_fp16.h>
#include <cstdint>

#define DI __device__ __forceinline__

// ---------------- problem dims ----------------
constexpr int Mdim = 16384;   // B*S
constexpr int Kdim = 2048;    // IN
constexpr int Ndim = 2048;    // OUT
constexpr int LR   = 128;     // L*R
constexpr int Rr   = 32;

// ---------------- scratch ----------------
__device__ uint4 g_xh_raw[(size_t)Mdim * Kdim * 2 / 16];   // fp16 x      (64 MB)
__device__ uint4 g_wh_raw[(size_t)Ndim * Kdim * 2 / 16];   // fp16 W_eff  (8 MB)

// ---------------- PTX helpers (family-portable only) ----------------
DI uint32_t smem_u32(const void* p) {
    uint32_t a;
    asm("{ .reg .u64 t; cvta.to.shared.u64 t, %1; cvt.u32.u64 %0, t; }" : "=r"(a) : "l"(p));
    return a;
}
DI void cp_async16(uint32_t dst, const void* src) {
    asm volatile("cp.async.cg.shared.global [%0], [%1], 16;" :: "r"(dst), "l"(src) : "memory");
}
DI void cp_commit() { asm volatile("cp.async.commit_group;" ::: "memory"); }
template <int Nn> DI void cp_wait() { asm volatile("cp.async.wait_group %0;" :: "n"(Nn) : "memory"); }

DI void ldmatrix_x4(uint32_t* r, uint32_t addr) {
    asm volatile("ldmatrix.sync.aligned.m8n8.x4.shared.b16 {%0,%1,%2,%3}, [%4];"
                 : "=r"(r[0]), "=r"(r[1]), "=r"(r[2]), "=r"(r[3]) : "r"(addr));
}
DI void mma16816(float* c, const uint32_t* a, uint32_t b0, uint32_t b1) {
    asm volatile(
        "mma.sync.aligned.m16n8k16.row.col.f32.f16.f16.f32 "
        "{%0,%1,%2,%3}, {%4,%5,%6,%7}, {%8,%9}, {%0,%1,%2,%3};"
        : "+f"(c[0]), "+f"(c[1]), "+f"(c[2]), "+f"(c[3])
        : "r"(a[0]), "r"(a[1]), "r"(a[2]), "r"(a[3]), "r"(b0), "r"(b1));
}
DI uint32_t tile_off(int row, int c) { return (uint32_t)(row * 128) + (uint32_t)(((c ^ (row & 7)) << 4)); }
DI uint32_t swz128(uint32_t b) { return b ^ ((b >> 3) & 0x70); }

// ============================================================
// Fused pre-pass kernel (unchanged):
//   blocks [0, 1024):    W_eff = W + sum_l s_l * up_l @ down_l  -> fp16
//   blocks [1024, 5120): x fp32 -> fp16
// ============================================================
constexpr int WEFF_BLOCKS = (Ndim / 64) * (Kdim / 64);   // 1024
constexpr int CONV_BLOCKS = 4096;
constexpr int US_STRIDE = 68;
constexpr int PREP_SMEM = (LR * US_STRIDE + LR * 64) * 4;  // 67584 B

__global__ void __launch_bounds__(256) k_prep(const float* __restrict__ x,
                                              const float* __restrict__ weight,
                                              const float* __restrict__ downs,
                                              const float* __restrict__ ups,
                                              const float* __restrict__ scales) {
    const int tid = threadIdx.x;

    if (blockIdx.x >= WEFF_BLOCKS) {
        size_t i = (size_t)(blockIdx.x - WEFF_BLOCKS) * 256 + tid;
        const size_t stride = (size_t)CONV_BLOCKS * 256;
        const float4* x4 = (const float4*)x;
        uint2* o4 = (uint2*)g_xh_raw;
        const size_t n4 = (size_t)Mdim * Kdim / 4;
        for (; i < n4; i += stride) {
            float4 v = x4[i];
            __half2 a = __floats2half2_rn(v.x, v.y);
            __half2 b = __floats2half2_rn(v.z, v.w);
            uint2 u;
            u.x = *(uint32_t*)&a;
            u.y = *(uint32_t*)&b;
            o4[i] = u;
        }
        return;
    }

    extern __shared__ float wsm[];
    float* Us = wsm;                   // [128][US_STRIDE]
    float* Ds = wsm + LR * US_STRIDE;  // [128][64]
    const int I0 = (blockIdx.x & 31) * 64;
    const int O0 = (blockIdx.x >> 5) * 64;

    {
        const int r = tid & 31, ob = tid >> 5;
#pragma unroll
        for (int l = 0; l < 4; l++) {
            float s = scales[l];
            const float* up_l = ups + (size_t)l * Ndim * Rr;
#pragma unroll
            for (int it = 0; it < 8; it++) {
                int o = it * 8 + ob;
                Us[(l * 32 + r) * US_STRIDE + o] = s * up_l[(size_t)(O0 + o) * Rr + r];
            }
        }
    }
    for (int c = tid; c < LR * 16; c += 256) {
        int k = c >> 4, f = c & 15;
        *(float4*)&Ds[k * 64 + f * 4] = *(const float4*)&downs[(size_t)k * Kdim + I0 + f * 4];
    }
    __syncthreads();

    const int to = tid >> 4, ti = tid & 15;
    float acc[4][4];
#pragma unroll
    for (int a = 0; a < 4; a++)
#pragma unroll
        for (int b = 0; b < 4; b++) acc[a][b] = 0.f;

#pragma unroll 4
    for (int k = 0; k < LR; k++) {
        float4 u = *(const float4*)&Us[k * US_STRIDE + to * 4];
        float4 d = *(const float4*)&Ds[k * 64 + ti * 4];
        float uu[4] = {u.x, u.y, u.z, u.w};
        float dd[4] = {d.x, d.y, d.z, d.w};
#pragma unroll
        for (int a = 0; a < 4; a++)
#pragma unroll
            for (int b = 0; b < 4; b++) acc[a][b] += uu[a] * dd[b];
    }

    __half* gw = (__half*)g_wh_raw;
#pragma unroll
    for (int a = 0; a < 4; a++) {
        int o = O0 + to * 4 + a;
        float4 wv = *(const float4*)&weight[(size_t)o * Kdim + I0 + ti * 4];
        __half2 p0 = __floats2half2_rn(acc[a][0] + wv.x, acc[a][1] + wv.y);
        __half2 p1 = __floats2half2_rn(acc[a][2] + wv.z, acc[a][3] + wv.w);
        uint2 u;
        u.x = *(uint32_t*)&p0;
        u.y = *(uint32_t*)&p1;
        *(uint2*)&gw[(size_t)o * Kdim + I0 + ti * 4] = u;
    }
}

// ============================================================
// Main GEMM: y = xh @ Wh^T + bias
//   4 warps (2x2), warp tile 64x64, BM=BN=128, BK=64, 3 stages.
//   Fragment double-buffer across ks-steps + cp.async scattered
//   over the 4 ks-steps to keep the tensor pipe fed.
// ============================================================
constexpr int BK = 64;
constexpr int STAGES = 3;
constexpr int NK = Kdim / BK;                    // 32
constexpr int AB_BYTES = 128 * 128;              // 16 KB
constexpr int STG_BYTES = 2 * AB_BYTES;          // 32 KB
constexpr int GEMM_SMEM = STAGES * STG_BYTES;    // 96 KB

__global__ void __launch_bounds__(128, 2) k_gemm(const float* __restrict__ bias,
                                                 float* __restrict__ out) {
    extern __shared__ char smem[];
    const uint32_t sb = smem_u32(smem);
    const int tid = threadIdx.x;
    const int wid = tid >> 5, lane = tid & 31;
    const int M0 = blockIdx.y * 128, N0 = blockIdx.x * 128;

    const int warp_m = (wid & 1) * 64;
    const int warp_n = (wid >> 1) * 64;

    const __half* gA = (const __half*)g_xh_raw;
    const __half* gB = (const __half*)g_wh_raw;

    // full-stage load (prologue only)
    auto load_stage = [&](int s, int kk) {
        const uint32_t base = sb + s * STG_BYTES;
        const int k0 = kk * BK;
#pragma unroll
        for (int it = 0; it < 8; it++) {
            int c = tid + it * 128;
            int row = c >> 3, col = c & 7;
            cp_async16(base + swz128(row * 128 + col * 16),
                       gA + (size_t)(M0 + row) * Kdim + k0 + col * 8);
        }
#pragma unroll
        for (int it = 0; it < 8; it++) {
            int c = tid + it * 128;
            int row = c >> 3, col = c & 7;
            cp_async16(base + AB_BYTES + swz128(row * 128 + col * 16),
                       gB + (size_t)(N0 + row) * Kdim + k0 + col * 8);
        }
    };

    float acc[4][8][4];
#pragma unroll
    for (int mt = 0; mt < 4; mt++)
#pragma unroll
        for (int nt = 0; nt < 8; nt++)
#pragma unroll
            for (int c = 0; c < 4; c++) acc[mt][nt][c] = 0.f;

    load_stage(0, 0); cp_commit();
    load_stage(1, 1); cp_commit();

    const int lane15 = lane & 15;
    const int laneHi = lane >> 4;
    int rowA[4], rowB[4];
#pragma unroll
    for (int mt = 0; mt < 4; mt++) rowA[mt] = warp_m + mt * 16 + lane15;
#pragma unroll
    for (int np = 0; np < 4; np++) rowB[np] = warp_n + np * 16 + lane15;

#define LOAD_FRAGS(abuf, bbuf, ks_)                                              \
    do {                                                                         \
        _Pragma("unroll")                                                        \
        for (int mt = 0; mt < 4; mt++)                                           \
            ldmatrix_x4((abuf)[mt], Ab + tile_off(rowA[mt], (ks_) * 2 + laneHi)); \
        _Pragma("unroll")                                                        \
        for (int np = 0; np < 4; np++)                                           \
            ldmatrix_x4((bbuf)[np], Bb + tile_off(rowB[np], (ks_) * 2 + laneHi)); \
    } while (0)

    for (int k = 0; k < NK; k++) {
        cp_wait<STAGES - 2>();
        __syncthreads();

        const int s = k % STAGES;
        const uint32_t Ab = sb + s * STG_BYTES;
        const uint32_t Bb = Ab + AB_BYTES;

        const int kn = k + STAGES - 1;
        const bool do_load = (kn < NK);
        const int sn = kn % STAGES;
        const uint32_t nbase = sb + sn * STG_BYTES;
        const int nk0 = (kn < NK ? kn : 0) * BK;

        uint32_t a[2][4][4], b[2][4][4];
        LOAD_FRAGS(a[0], b[0], 0);

#pragma unroll
        for (int ks = 0; ks < 4; ks++) {
            // scatter 1/4 of the next-stage cp.async into this ks-step
            if (do_load) {
#pragma unroll
                for (int it = ks * 2; it < ks * 2 + 2; it++) {
                    int c = tid + it * 128;
                    int row = c >> 3, col = c & 7;
                    cp_async16(nbase + swz128(row * 128 + col * 16),
                               gA + (size_t)(M0 + row) * Kdim + nk0 + col * 8);
                    cp_async16(nbase + AB_BYTES + swz128(row * 128 + col * 16),
                               gB + (size_t)(N0 + row) * Kdim + nk0 + col * 8);
                }
            }
            const int cur = ks & 1, nxt = cur ^ 1;
            if (ks < 3) LOAD_FRAGS(a[nxt], b[nxt], ks + 1);
#pragma unroll
            for (int mt = 0; mt < 4; mt++)
#pragma unroll
                for (int nt = 0; nt < 8; nt++) {
                    const int np = nt >> 1, half = nt & 1;
                    mma16816(acc[mt][nt], a[cur][mt], b[cur][np][half], b[cur][np][2 + half]);
                }
        }
        cp_commit();
    }
#undef LOAD_FRAGS

    // epilogue
    const int gq = lane >> 2, rq = lane & 3;
#pragma unroll
    for (int mt = 0; mt < 4; mt++) {
#pragma unroll
        for (int nt = 0; nt < 8; nt++) {
            int m = M0 + warp_m + mt * 16 + gq;
            int n = N0 + warp_n + nt * 8 + rq * 2;
            float2 bv = *(const float2*)&bias[n];
            float2 v0, v1;
            v0.x = acc[mt][nt][0] + bv.x;
            v0.y = acc[mt][nt][1] + bv.y;
            v1.x = acc[mt][nt][2] + bv.x;
            v1.y = acc[mt][nt][3] + bv.y;
            *(float2*)&out[(size_t)m * Ndim + n] = v0;
            *(float2*)&out[(size_t)(m + 8) * Ndim + n] = v1;
        }
    }
}

// ============================================================
// launch
// ============================================================
extern "C" void kernel_launch(void* const* d_in, const int* in_sizes, int n_in,
                              void* d_out, int out_size) {
    const float* x      = (const float*)d_in[0];
    const float* weight = (const float*)d_in[1];
    const float* bias   = (const float*)d_in[2];
    const float* downs  = (const float*)d_in[3];
    const float* ups    = (const float*)d_in[4];
    const float* scales = (const float*)d_in[5];
    float* out = (float*)d_out;

    cudaFuncSetAttribute(k_gemm, cudaFuncAttributeMaxDynamicSharedMemorySize, GEMM_SMEM);
    cudaFuncSetAttribute(k_prep, cudaFuncAttributeMaxDynamicSharedMemorySize, PREP_SMEM);

    k_prep<<<WEFF_BLOCKS + CONV_BLOCKS, 256, PREP_SMEM>>>(x, weight, downs, ups, scales);
    k_gemm<<<dim3(Ndim / 128, Mdim / 128), 128, GEMM_SMEM>>>(bias, out);
}